// round 9
// baseline (speedup 1.0000x reference)
#include <cuda_runtime.h>
#include <cuda_bf16.h>
#include <cstdint>

#define NPTS 1048576
#define NTASKS (2 * NPTS)            // 2 tasks per point, 8 nbrs each
#define GRID_MAIN 888                // 148 SMs x 6 CTAs
#define NTHREADS 256
#define NTILES (NTASKS / NTHREADS)   // 8192 tiles of 256 tasks
#define TILE_HALF 8192               // bytes of idx (= bytes of orig) per tile
#define TILE_BYTES (2 * TILE_HALF)   // 16384

// Padded points: 16B rows -> each random gather = exactly one L1tex
// wavefront / one 32B L2 sector.
__device__ float4 g_pts4[NPTS];
__device__ double g_acc;
__device__ unsigned int g_ticket;

__device__ __forceinline__ uint32_t smem_u32(const void* p) {
    uint32_t a;
    asm("{ .reg .u64 t; cvta.to.shared.u64 t, %1; cvt.u32.u64 %0, t; }"
        : "=r"(a) : "l"(p));
    return a;
}

#define MBAR_INIT(a, c) \
    asm volatile("mbarrier.init.shared.b64 [%0], %1;" :: "r"(a), "r"(c) : "memory")
#define MBAR_EXPECT_TX(a, b) \
    asm volatile("mbarrier.arrive.expect_tx.shared.b64 _, [%0], %1;" :: "r"(a), "r"(b) : "memory")
#define MBAR_WAIT(a, ph)                                                           \
    asm volatile("{\n\t.reg .pred P;\n\t"                                          \
                 "W_%=: mbarrier.try_wait.parity.acquire.cta.shared::cta.b64 "     \
                 "P, [%0], %1, 0x989680;\n\t"                                      \
                 "@P bra D_%=;\n\t bra W_%=;\n\tD_%=:\n\t}"                        \
                 :: "r"(a), "r"(ph) : "memory")
#define BULK_G2S(dst, src, bytes, mbar)                                            \
    asm volatile("cp.async.bulk.shared::cluster.global.mbarrier::complete_tx::bytes " \
                 "[%0], [%1], %2, [%3];"                                           \
                 :: "r"(dst), "l"(src), "r"(bytes), "r"(mbar) : "memory")

// Kernel 1: pad [N,3] f32 -> [N] float4 (4 points/thread, R7 version) and
// reset accumulator + ticket every replay. PDL trigger after stores.
__global__ void __launch_bounds__(256) pad_points_kernel(const float* __restrict__ pts) {
    int i = blockIdx.x * blockDim.x + threadIdx.x;   // 0 .. 262143
    if (i == 0) { g_acc = 0.0; g_ticket = 0u; }

    const float4* p4 = reinterpret_cast<const float4*>(pts) + 3 * i;
    float4 a = p4[0];
    float4 b = p4[1];
    float4 c = p4[2];

    int o = 4 * i;
    g_pts4[o + 0] = make_float4(a.x, a.y, a.z, 0.0f);
    g_pts4[o + 1] = make_float4(a.w, b.x, b.y, 0.0f);
    g_pts4[o + 2] = make_float4(b.z, b.w, c.x, 0.0f);
    g_pts4[o + 3] = make_float4(c.y, c.z, c.w, 0.0f);

    cudaTriggerProgrammaticLaunchCompletion();
}

// Kernel 2: persistent; idx/orig streamed via double-buffered TMA bulk
// copies into SMEM (bypasses the L1tex wavefront path, which the random
// 16B gathers saturate). Compute body identical to the proven R7 loop.
__global__ void __launch_bounds__(NTHREADS, 6) neighbour_loss_kernel(
    const int* __restrict__ idx,
    const float* __restrict__ orig,
    float* __restrict__ out)
{
    __shared__ alignas(128) int4   s_idx[2][2 * NTHREADS];   // 2 x 8KB
    __shared__ alignas(128) float4 s_org[2][2 * NTHREADS];   // 2 x 8KB
    __shared__ alignas(8)  uint64_t s_mbar[2];

    const int tid = threadIdx.x;
    const uint32_t mb0 = smem_u32(&s_mbar[0]);
    const uint32_t mb1 = smem_u32(&s_mbar[1]);
    const char* idx_b = (const char*)idx;
    const char* org_b = (const char*)orig;

    if (tid == 0) {
        MBAR_INIT(mb0, 1);
        MBAR_INIT(mb1, 1);
        asm volatile("fence.proxy.async.shared::cta;" ::: "memory");
    }
    __syncthreads();

    // Issue tile0 into stage 0 — independent of the pad kernel's output,
    // so it overlaps the pad kernel under PDL.
    const int tile0 = blockIdx.x;
    if (tid == 0) {
        MBAR_EXPECT_TX(mb0, TILE_BYTES);
        BULK_G2S(smem_u32(&s_idx[0][0]), idx_b + (size_t)tile0 * TILE_HALF, TILE_HALF, mb0);
        BULK_G2S(smem_u32(&s_org[0][0]), org_b + (size_t)tile0 * TILE_HALF, TILE_HALF, mb0);
    }

    // Gathers below need g_pts4 -> wait for pad kernel.
    cudaGridDependencySynchronize();

    float tsum = 0.0f;
    unsigned ph0 = 0u, ph1 = 0u;
    int s = 0;
    for (int k = tile0; k < NTILES; k += GRID_MAIN, s ^= 1) {
        // Prefetch next tile into the other stage (its previous contents
        // were fully consumed before the __syncthreads of 2 iters ago).
        int kn = k + GRID_MAIN;
        if (kn < NTILES && tid == 0) {
            uint32_t m = s ? mb0 : mb1;
            int so = s ^ 1;
            MBAR_EXPECT_TX(m, TILE_BYTES);
            BULK_G2S(smem_u32(&s_idx[so][0]), idx_b + (size_t)kn * TILE_HALF, TILE_HALF, m);
            BULK_G2S(smem_u32(&s_org[so][0]), org_b + (size_t)kn * TILE_HALF, TILE_HALF, m);
        }

        // Wait for current stage's data.
        if (s) { MBAR_WAIT(mb1, ph1); ph1 ^= 1u; }
        else   { MBAR_WAIT(mb0, ph0); ph0 ^= 1u; }

        // Task t_g = k*256 + tid; its 8 neighbour indices / distances.
        int4 i0 = s_idx[s][2 * tid + 0];
        int4 i1 = s_idx[s][2 * tid + 1];

        // 8 independent 16B gathers — all outstanding simultaneously.
        float4 q0 = __ldg(&g_pts4[i0.x]);
        float4 q1 = __ldg(&g_pts4[i0.y]);
        float4 q2 = __ldg(&g_pts4[i0.z]);
        float4 q3 = __ldg(&g_pts4[i0.w]);
        float4 q4 = __ldg(&g_pts4[i1.x]);
        float4 q5 = __ldg(&g_pts4[i1.y]);
        float4 q6 = __ldg(&g_pts4[i1.z]);
        float4 q7 = __ldg(&g_pts4[i1.w]);

        float4 o0 = s_org[s][2 * tid + 0];
        float4 o1 = s_org[s][2 * tid + 1];
        float4 p  = __ldg(&g_pts4[(k * NTHREADS + tid) >> 1]);

        float dx, dy, dz, curr, e;
        #define ACC(q, ov)                                        \
            dx = p.x - q.x; dy = p.y - q.y; dz = p.z - q.z;       \
            curr = fmaf(dx, dx, fmaf(dy, dy, dz * dz));           \
            e = curr - ov;                                        \
            tsum = fmaf(e, e, tsum);
        ACC(q0, o0.x) ACC(q1, o0.y) ACC(q2, o0.z) ACC(q3, o0.w)
        ACC(q4, o1.x) ACC(q5, o1.y) ACC(q6, o1.z) ACC(q7, o1.w)
        #undef ACC

        // All threads done reading stage s before it can be overwritten.
        __syncthreads();
    }

    // ---- reduce: warp -> block -> global; fused finalize ----
    #pragma unroll
    for (int off = 16; off > 0; off >>= 1)
        tsum += __shfl_down_sync(0xFFFFFFFFu, tsum, off);

    __shared__ float warp_sums[8];
    int lane = tid & 31;
    int wid  = tid >> 5;
    if (lane == 0) warp_sums[wid] = tsum;
    __syncthreads();
    if (wid == 0) {
        float bs = (lane < 8) ? warp_sums[lane] : 0.0f;
        #pragma unroll
        for (int off = 4; off > 0; off >>= 1)
            bs += __shfl_down_sync(0xFFFFFFFFu, bs, off);
        if (lane == 0) {
            atomicAdd(&g_acc, (double)bs);
            __threadfence();
            unsigned tk = atomicAdd(&g_ticket, 1u);
            if (tk == GRID_MAIN - 1) {
                double total = atomicAdd(&g_acc, 0.0);   // atomic read
                out[0] = (float)(total * (100000.0 / 16777216.0));
            }
        }
    }
}

extern "C" void kernel_launch(void* const* d_in, const int* in_sizes, int n_in,
                              void* d_out, int out_size) {
    const float* points = (const float*)d_in[0];
    const int*   nidx   = (const int*)d_in[1];
    const float* orig   = (const float*)d_in[2];
    float* out = (float*)d_out;

    (void)in_sizes; (void)n_in; (void)out_size;

    pad_points_kernel<<<1024, 256>>>(points);   // 4 pts/thread

    // Main kernel with Programmatic Dependent Launch: its launch/ramp and
    // first TMA tile overlap the pad kernel; cudaGridDependencySynchronize()
    // inside the kernel gates only the gathers.
    cudaLaunchConfig_t cfg = {};
    cfg.gridDim  = dim3(GRID_MAIN);
    cfg.blockDim = dim3(NTHREADS);
    cfg.dynamicSmemBytes = 0;
    cfg.stream = 0;
    cudaLaunchAttribute attrs[1];
    attrs[0].id = cudaLaunchAttributeProgrammaticStreamSerialization;
    attrs[0].val.programmaticStreamSerializationAllowed = 1;
    cfg.attrs = attrs;
    cfg.numAttrs = 1;
    cudaLaunchKernelEx(&cfg, neighbour_loss_kernel, nidx, orig, out);
}

// round 10
// speedup vs baseline: 1.8154x; 1.8154x over previous
#include <cuda_runtime.h>
#include <cuda_bf16.h>

#define NPTS 1048576
#define KNEI 16
#define NTASKS (2 * NPTS)          // 2 tasks per point, 8 nbrs each
#define GRID_MAIN 888              // 148 SMs x 6 CTAs (reg cap via launch_bounds)
#define NTHREADS 256

// Padded points: 16B rows -> each random gather = exactly one L1tex
// wavefront / one 32B L2 sector.
__device__ float4 g_pts4[NPTS];
__device__ double g_acc;
__device__ unsigned int g_ticket;

// Kernel 1: pad [N,3] f32 -> [N] float4 (4 points per thread) and reset
// accumulator + ticket (every graph replay). PDL trigger fires once this
// block's stores are issued so the main kernel can ramp up under our tail.
__global__ void __launch_bounds__(256) pad_points_kernel(const float* __restrict__ pts) {
    int i = blockIdx.x * blockDim.x + threadIdx.x;   // 0 .. 262143
    if (i == 0) { g_acc = 0.0; g_ticket = 0u; }

    const float4* p4 = reinterpret_cast<const float4*>(pts) + 3 * i;
    float4 a = __ldcs(&p4[0]);
    float4 b = __ldcs(&p4[1]);
    float4 c = __ldcs(&p4[2]);

    int o = 4 * i;
    g_pts4[o + 0] = make_float4(a.x, a.y, a.z, 0.0f);
    g_pts4[o + 1] = make_float4(a.w, b.x, b.y, 0.0f);
    g_pts4[o + 2] = make_float4(b.z, b.w, c.x, 0.0f);
    g_pts4[o + 3] = make_float4(c.y, c.z, c.w, 0.0f);

    cudaTriggerProgrammaticLaunchCompletion();
}

// Kernel 2: persistent grid-stride over 2M pair-tasks (8 neighbours each).
// Proven 40-reg barrier-free loop (R4/R7); PDL sync at the top only.
// Streamed idx/orig loads use evict-first (__ldcs) to keep L1 capacity for
// the randomly-gathered point lines.
__global__ void __launch_bounds__(NTHREADS, 6) neighbour_loss_kernel(
    const int* __restrict__ idx,
    const float* __restrict__ orig,
    float* __restrict__ out)
{
    // Wait for pad kernel's results (PDL overlap happens before this point).
    cudaGridDependencySynchronize();

    const int stride = GRID_MAIN * NTHREADS;
    float tsum = 0.0f;

    for (int t = blockIdx.x * NTHREADS + threadIdx.x; t < NTASKS; t += stride) {
        int n = t >> 1;   // point id

        const int4* idx4 = reinterpret_cast<const int4*>(idx) + t * 2;
        int4 i0 = __ldcs(&idx4[0]);
        int4 i1 = __ldcs(&idx4[1]);

        // 8 independent 16B gathers — all outstanding simultaneously.
        float4 q0 = __ldg(&g_pts4[i0.x]);
        float4 q1 = __ldg(&g_pts4[i0.y]);
        float4 q2 = __ldg(&g_pts4[i0.z]);
        float4 q3 = __ldg(&g_pts4[i0.w]);
        float4 q4 = __ldg(&g_pts4[i1.x]);
        float4 q5 = __ldg(&g_pts4[i1.y]);
        float4 q6 = __ldg(&g_pts4[i1.z]);
        float4 q7 = __ldg(&g_pts4[i1.w]);

        const float4* orig4 = reinterpret_cast<const float4*>(orig) + t * 2;
        float4 o0 = __ldcs(&orig4[0]);
        float4 o1 = __ldcs(&orig4[1]);
        float4 p  = g_pts4[n];

        float dx, dy, dz, curr, e;
        #define ACC(q, ov)                                        \
            dx = p.x - q.x; dy = p.y - q.y; dz = p.z - q.z;       \
            curr = fmaf(dx, dx, fmaf(dy, dy, dz * dz));           \
            e = curr - ov;                                        \
            tsum = fmaf(e, e, tsum);
        ACC(q0, o0.x) ACC(q1, o0.y) ACC(q2, o0.z) ACC(q3, o0.w)
        ACC(q4, o1.x) ACC(q5, o1.y) ACC(q6, o1.z) ACC(q7, o1.w)
        #undef ACC
    }

    // ---- reduce: warp -> block -> global; fused finalize ----
    #pragma unroll
    for (int off = 16; off > 0; off >>= 1)
        tsum += __shfl_down_sync(0xFFFFFFFFu, tsum, off);

    __shared__ float warp_sums[8];
    int lane = threadIdx.x & 31;
    int wid  = threadIdx.x >> 5;
    if (lane == 0) warp_sums[wid] = tsum;
    __syncthreads();
    if (wid == 0) {
        float bs = (lane < 8) ? warp_sums[lane] : 0.0f;
        #pragma unroll
        for (int off = 4; off > 0; off >>= 1)
            bs += __shfl_down_sync(0xFFFFFFFFu, bs, off);
        if (lane == 0) {
            atomicAdd(&g_acc, (double)bs);
            __threadfence();
            unsigned tk = atomicAdd(&g_ticket, 1u);
            if (tk == GRID_MAIN - 1) {
                double total = atomicAdd(&g_acc, 0.0);   // atomic read
                out[0] = (float)(total * (100000.0 / 16777216.0));
            }
        }
    }
}

extern "C" void kernel_launch(void* const* d_in, const int* in_sizes, int n_in,
                              void* d_out, int out_size) {
    const float* points = (const float*)d_in[0];
    const int*   nidx   = (const int*)d_in[1];
    const float* orig   = (const float*)d_in[2];
    float* out = (float*)d_out;

    (void)in_sizes; (void)n_in; (void)out_size;

    pad_points_kernel<<<1024, 256>>>(points);   // 4 pts/thread

    // Main kernel with Programmatic Dependent Launch: its launch/ramp
    // overlaps the pad kernel's tail; cudaGridDependencySynchronize()
    // inside the kernel enforces correctness.
    cudaLaunchConfig_t cfg = {};
    cfg.gridDim  = dim3(GRID_MAIN);
    cfg.blockDim = dim3(NTHREADS);
    cfg.dynamicSmemBytes = 0;
    cfg.stream = 0;
    cudaLaunchAttribute attrs[1];
    attrs[0].id = cudaLaunchAttributeProgrammaticStreamSerialization;
    attrs[0].val.programmaticStreamSerializationAllowed = 1;
    cfg.attrs = attrs;
    cfg.numAttrs = 1;
    cudaLaunchKernelEx(&cfg, neighbour_loss_kernel, nidx, orig, out);
}

// round 11
// speedup vs baseline: 1.8597x; 1.0244x over previous
#include <cuda_runtime.h>
#include <cuda_bf16.h>

#define NPTS 1048576
#define KNEI 16
#define NTASKS (2 * NPTS)          // 2 tasks per point, 8 nbrs each
#define GRID_MAIN 888              // 148 SMs x 6 CTAs (reg cap via launch_bounds)
#define NTHREADS 256

// Padded points: 16B rows -> each random gather = exactly one L1tex
// wavefront / one 32B L2 sector.
__device__ float4 g_pts4[NPTS];
__device__ double g_acc;
__device__ unsigned int g_ticket;

// Kernel 1: pad [N,3] f32 -> [N] float4 (4 points per thread) and reset
// accumulator + ticket (every graph replay). PDL trigger fires once this
// block's stores are issued so the main kernel can ramp up under our tail.
__global__ void __launch_bounds__(256) pad_points_kernel(const float* __restrict__ pts) {
    int i = blockIdx.x * blockDim.x + threadIdx.x;   // 0 .. 262143
    if (i == 0) { g_acc = 0.0; g_ticket = 0u; }

    const float4* p4 = reinterpret_cast<const float4*>(pts) + 3 * i;
    float4 a = p4[0];
    float4 b = p4[1];
    float4 c = p4[2];

    int o = 4 * i;
    g_pts4[o + 0] = make_float4(a.x, a.y, a.z, 0.0f);
    g_pts4[o + 1] = make_float4(a.w, b.x, b.y, 0.0f);
    g_pts4[o + 2] = make_float4(b.z, b.w, c.x, 0.0f);
    g_pts4[o + 3] = make_float4(c.y, c.z, c.w, 0.0f);

    cudaTriggerProgrammaticLaunchCompletion();
}

// Kernel 2: persistent grid-stride over 2M pair-tasks (8 neighbours each).
// Proven 40-reg barrier-free loop; PDL sync at the top only. Plain loads
// throughout (every cache-hint / staging variant measured slower).
__global__ void __launch_bounds__(NTHREADS, 6) neighbour_loss_kernel(
    const int* __restrict__ idx,
    const float* __restrict__ orig,
    float* __restrict__ out)
{
    // Wait for pad kernel's results (PDL overlap happens before this point).
    cudaGridDependencySynchronize();

    const int stride = GRID_MAIN * NTHREADS;
    float tsum = 0.0f;

    for (int t = blockIdx.x * NTHREADS + threadIdx.x; t < NTASKS; t += stride) {
        int n = t >> 1;   // point id

        const int4* idx4 = reinterpret_cast<const int4*>(idx) + t * 2;
        int4 i0 = idx4[0];
        int4 i1 = idx4[1];

        // 8 independent 16B gathers — all outstanding simultaneously.
        float4 q0 = __ldg(&g_pts4[i0.x]);
        float4 q1 = __ldg(&g_pts4[i0.y]);
        float4 q2 = __ldg(&g_pts4[i0.z]);
        float4 q3 = __ldg(&g_pts4[i0.w]);
        float4 q4 = __ldg(&g_pts4[i1.x]);
        float4 q5 = __ldg(&g_pts4[i1.y]);
        float4 q6 = __ldg(&g_pts4[i1.z]);
        float4 q7 = __ldg(&g_pts4[i1.w]);

        const float4* orig4 = reinterpret_cast<const float4*>(orig) + t * 2;
        float4 o0 = orig4[0];
        float4 o1 = orig4[1];
        float4 p  = g_pts4[n];

        float dx, dy, dz, curr, e;
        #define ACC(q, ov)                                        \
            dx = p.x - q.x; dy = p.y - q.y; dz = p.z - q.z;       \
            curr = fmaf(dx, dx, fmaf(dy, dy, dz * dz));           \
            e = curr - ov;                                        \
            tsum = fmaf(e, e, tsum);
        ACC(q0, o0.x) ACC(q1, o0.y) ACC(q2, o0.z) ACC(q3, o0.w)
        ACC(q4, o1.x) ACC(q5, o1.y) ACC(q6, o1.z) ACC(q7, o1.w)
        #undef ACC
    }

    // ---- reduce: warp -> block -> global; fused finalize ----
    #pragma unroll
    for (int off = 16; off > 0; off >>= 1)
        tsum += __shfl_down_sync(0xFFFFFFFFu, tsum, off);

    __shared__ float warp_sums[8];
    int lane = threadIdx.x & 31;
    int wid  = threadIdx.x >> 5;
    if (lane == 0) warp_sums[wid] = tsum;
    __syncthreads();
    if (wid == 0) {
        float bs = (lane < 8) ? warp_sums[lane] : 0.0f;
        #pragma unroll
        for (int off = 4; off > 0; off >>= 1)
            bs += __shfl_down_sync(0xFFFFFFFFu, bs, off);
        if (lane == 0) {
            atomicAdd(&g_acc, (double)bs);
            __threadfence();
            unsigned tk = atomicAdd(&g_ticket, 1u);
            if (tk == GRID_MAIN - 1) {
                double total = atomicAdd(&g_acc, 0.0);   // atomic read
                out[0] = (float)(total * (100000.0 / 16777216.0));
            }
        }
    }
}

extern "C" void kernel_launch(void* const* d_in, const int* in_sizes, int n_in,
                              void* d_out, int out_size) {
    const float* points = (const float*)d_in[0];
    const int*   nidx   = (const int*)d_in[1];
    const float* orig   = (const float*)d_in[2];
    float* out = (float*)d_out;

    (void)in_sizes; (void)n_in; (void)out_size;

    pad_points_kernel<<<1024, 256>>>(points);   // 4 pts/thread

    // Main kernel with Programmatic Dependent Launch: its launch/ramp
    // overlaps the pad kernel's tail; cudaGridDependencySynchronize()
    // inside the kernel enforces correctness.
    cudaLaunchConfig_t cfg = {};
    cfg.gridDim  = dim3(GRID_MAIN);
    cfg.blockDim = dim3(NTHREADS);
    cfg.dynamicSmemBytes = 0;
    cfg.stream = 0;
    cudaLaunchAttribute attrs[1];
    attrs[0].id = cudaLaunchAttributeProgrammaticStreamSerialization;
    attrs[0].val.programmaticStreamSerializationAllowed = 1;
    cfg.attrs = attrs;
    cfg.numAttrs = 1;
    cudaLaunchKernelEx(&cfg, neighbour_loss_kernel, nidx, orig, out);
}